// round 7
// baseline (speedup 1.0000x reference)
#include <cuda_runtime.h>
#include <cuda_fp16.h>

// fp16 pyramid, levels 0..7. Texels/plane: 512^2 + 256^2 + ... + 4^2 = 349520.
#define T_ALL 349520
__device__ __half g_pyrh[3 * T_ALL * 16];     // 33.6 MB
__device__ float4 g_l4[3 * 1024 * 4];         // fp32 level 4 (32x32/plane), c4-sliced
__device__ unsigned g_ctr = 0;

// texel offset of level l (0..7) within a plane's fp16 region
__constant__ int c_off[8] = {0, 262144, 327680, 344064, 348160, 349184, 349440, 349504};

__device__ __forceinline__ void st_h4(__half* p, float4 v) {
    __half2 a = __floats2half2_rn(v.x, v.y);
    __half2 b = __floats2half2_rn(v.z, v.w);
    uint2 u;
    u.x = *reinterpret_cast<unsigned*>(&a);
    u.y = *reinterpret_cast<unsigned*>(&b);
    *reinterpret_cast<uint2*>(p) = u;
}

__device__ __forceinline__ float4 avg4(float4 a, float4 b, float4 c, float4 d) {
    float4 r;
    r.x = (a.x + b.x + c.x + d.x) * 0.25f;
    r.y = (a.y + b.y + c.y + d.y) * 0.25f;
    r.z = (a.z + b.z + c.z + d.z) * 0.25f;
    r.w = (a.w + b.w + c.w + d.w) * 0.25f;
    return r;
}

// ---------------------------------------------------------------------------
// ds_fused: block = (plane, 16x16 L0 tile). Coalesced fm load into smem,
// fp16 L0 copy (coalesced), cascade L1..L4 in smem. Last block builds L5..L7.
// ---------------------------------------------------------------------------
__global__ void __launch_bounds__(256) ds_fused(const float4* __restrict__ fm) {
    __shared__ float4 s0[1024];   // 16x16 texels x 4 f4 (16KB)
    __shared__ float4 s1[256];    // 8x8
    __shared__ float4 s2[64];     // 4x4
    __shared__ float4 s3[16];     // 2x2
    __shared__ bool   isLast;

    const int b = blockIdx.x;
    const int tile = b & 1023;
    const int plane = b >> 10;
    const int tx = tile & 31, ty = tile >> 5;
    const int tid = threadIdx.x;

    const float4* src = fm + (size_t)plane * (512 * 512 * 4);
    __half* hp = g_pyrh + (size_t)plane * T_ALL * 16;

    // Load 16x16x4 = 1024 float4, 4 per thread; write fp16 L0 coalesced.
    #pragma unroll
    for (int i = 0; i < 4; ++i) {
        int idx = i * 256 + tid;
        int r = idx >> 6, o = idx & 63;          // o = texel_in_row*4 + c4
        float4 v = __ldg(src + (size_t)(ty * 16 + r) * 2048 + tx * 64 + o);
        s0[idx] = v;
        const size_t gtex = (size_t)(ty * 16 + r) * 512 + tx * 16 + (o >> 2);
        st_h4(hp + gtex * 16 + (o & 3) * 4, v);
    }
    __syncthreads();

    // L1: 8x8 texels x4
    {
        int c4 = tid & 3, x = (tid >> 2) & 7, y = tid >> 5;
        float4 v = avg4(s0[((2 * y) * 16 + 2 * x) * 4 + c4],
                        s0[((2 * y) * 16 + 2 * x + 1) * 4 + c4],
                        s0[((2 * y + 1) * 16 + 2 * x) * 4 + c4],
                        s0[((2 * y + 1) * 16 + 2 * x + 1) * 4 + c4]);
        s1[tid] = v;
        st_h4(hp + (size_t)(c_off[1] + (ty * 8 + y) * 256 + tx * 8 + x) * 16 + c4 * 4, v);
    }
    __syncthreads();

    // L2: 4x4 x4
    if (tid < 64) {
        int c4 = tid & 3, x = (tid >> 2) & 3, y = tid >> 4;
        float4 v = avg4(s1[((2 * y) * 8 + 2 * x) * 4 + c4],
                        s1[((2 * y) * 8 + 2 * x + 1) * 4 + c4],
                        s1[((2 * y + 1) * 8 + 2 * x) * 4 + c4],
                        s1[((2 * y + 1) * 8 + 2 * x + 1) * 4 + c4]);
        s2[tid] = v;
        st_h4(hp + (size_t)(c_off[2] + (ty * 4 + y) * 128 + tx * 4 + x) * 16 + c4 * 4, v);
    }
    __syncthreads();

    // L3: 2x2 x4
    if (tid < 16) {
        int c4 = tid & 3, x = (tid >> 2) & 1, y = tid >> 3;
        float4 v = avg4(s2[((2 * y) * 4 + 2 * x) * 4 + c4],
                        s2[((2 * y) * 4 + 2 * x + 1) * 4 + c4],
                        s2[((2 * y + 1) * 4 + 2 * x) * 4 + c4],
                        s2[((2 * y + 1) * 4 + 2 * x + 1) * 4 + c4]);
        s3[tid] = v;
        st_h4(hp + (size_t)(c_off[3] + (ty * 2 + y) * 64 + tx * 2 + x) * 16 + c4 * 4, v);
    }
    __syncthreads();

    // L4: one texel per tile
    if (tid < 4) {
        int c4 = tid;
        float4 v = avg4(s3[0 * 4 + c4], s3[1 * 4 + c4], s3[2 * 4 + c4], s3[3 * 4 + c4]);
        st_h4(hp + (size_t)(c_off[4] + ty * 32 + tx) * 16 + c4 * 4, v);
        g_l4[((size_t)plane * 1024 + ty * 32 + tx) * 4 + c4] = v;
    }

    // ---- last block builds L5..L7 from fp32 L4 ----
    if (tid == 0) {
        __threadfence();
        unsigned c = atomicAdd(&g_ctr, 1u);
        isLast = (c == (unsigned)(gridDim.x - 1));
    }
    __syncthreads();
    if (!isLast) return;
    if (tid == 0) g_ctr = 0;       // reset for next graph replay
    __threadfence();               // see all blocks' g_l4 writes

    for (int pl = 0; pl < 3; ++pl) {
        __half* hq = g_pyrh + (size_t)pl * T_ALL * 16;
        const float4* L4 = g_l4 + (size_t)pl * 1024 * 4;
        __syncthreads();
        // L5: 16x16 x4 = 1024 items
        for (int k = tid; k < 1024; k += 256) {
            int c4 = k & 3, x = (k >> 2) & 15, y = k >> 6;
            float4 v = avg4(L4[((2 * y) * 32 + 2 * x) * 4 + c4],
                            L4[((2 * y) * 32 + 2 * x + 1) * 4 + c4],
                            L4[((2 * y + 1) * 32 + 2 * x) * 4 + c4],
                            L4[((2 * y + 1) * 32 + 2 * x + 1) * 4 + c4]);
            s0[k] = v;
            st_h4(hq + (size_t)(c_off[5] + y * 16 + x) * 16 + c4 * 4, v);
        }
        __syncthreads();
        // L6: 8x8 x4 = 256 items
        {
            int c4 = tid & 3, x = (tid >> 2) & 7, y = tid >> 5;
            float4 v = avg4(s0[((2 * y) * 16 + 2 * x) * 4 + c4],
                            s0[((2 * y) * 16 + 2 * x + 1) * 4 + c4],
                            s0[((2 * y + 1) * 16 + 2 * x) * 4 + c4],
                            s0[((2 * y + 1) * 16 + 2 * x + 1) * 4 + c4]);
            st_h4(hq + (size_t)(c_off[6] + y * 8 + x) * 16 + c4 * 4, v);
        }
        // L7: 4x4 x4 via 4x4 box of L5
        if (tid < 64) {
            int c4 = tid & 3, x = (tid >> 2) & 3, y = tid >> 4;
            float4 acc = make_float4(0.f, 0.f, 0.f, 0.f);
            #pragma unroll
            for (int dy = 0; dy < 4; ++dy)
                #pragma unroll
                for (int dx = 0; dx < 4; ++dx) {
                    float4 t = s0[((4 * y + dy) * 16 + 4 * x + dx) * 4 + c4];
                    acc.x += t.x; acc.y += t.y; acc.z += t.z; acc.w += t.w;
                }
            float4 v = make_float4(acc.x * 0.0625f, acc.y * 0.0625f,
                                   acc.z * 0.0625f, acc.w * 0.0625f);
            st_h4(hq + (size_t)(c_off[7] + y * 4 + x) * 16 + c4 * 4, v);
        }
    }
}

// ---------------------------------------------------------------------------
// Sample: 4 lanes per (point, plane): lane = (cx, c2). Branchless.
// Packed-half2 exchange: 2 shfls per tap; each lane accumulates only its
// 4 output channels. Output stored with evict-first (__stcs) so the 100MB
// stream doesn't evict fm/pyramid from L2 across graph replays.
// ---------------------------------------------------------------------------
__global__ void __launch_bounds__(256) sample_kernel(
        const float* __restrict__ xin,
        const float* __restrict__ level,
        float4* __restrict__ out, int N3) {
    const int gid = blockIdx.x * blockDim.x + threadIdx.x;
    const int ps = gid >> 2;
    if (ps >= N3) return;
    const int sub = gid & 3;
    const int c2 = sub & 1;
    const int cx = sub >> 1;
    const int pt = ps / 3;
    const int plane = ps - pt * 3;

    const float xv = __ldg(xin + pt * 3 + 0);
    const float yv = __ldg(xin + pt * 3 + 1);
    const float zv = __ldg(xin + pt * 3 + 2);
    const float u = (plane == 0) ? yv : xv;
    const float v = (plane == 2) ? yv : zv;

    float lvl = fminf(fmaxf(__ldg(level + pt), 0.f), 7.f);
    const float l0f = floorf(lvl);
    const float f = lvl - l0f;
    const int l0 = (int)l0f;
    const int l1 = min(l0 + 1, 7);

    const uint4* pyr = reinterpret_cast<const uint4*>(g_pyrh) + (size_t)plane * T_ALL * 2;

    // ---- tap 0 addresses ----
    const int sz0 = 512 >> l0;
    const float px0 = u * (float)sz0 - 0.5f;
    const float py0 = v * (float)sz0 - 0.5f;
    const float x0f0 = floorf(px0), y0f0 = floorf(py0);
    const float fx0 = px0 - x0f0, fy0 = py0 - y0f0;
    const int sm0 = sz0 - 1;
    const int xa0 = min(max((int)x0f0, 0), sm0);
    const int xb0 = min(max((int)x0f0 + 1, 0), sm0);
    const int ya0 = min(max((int)y0f0, 0), sm0);
    const int yb0 = min(max((int)y0f0 + 1, 0), sm0);
    const int xc0 = cx ? xb0 : xa0;
    const uint4* b0 = pyr + c_off[l0] * 2;

    // ---- tap 1 addresses ----
    const int sz1 = 512 >> l1;
    const float px1 = u * (float)sz1 - 0.5f;
    const float py1 = v * (float)sz1 - 0.5f;
    const float x0f1 = floorf(px1), y0f1 = floorf(py1);
    const float fx1 = px1 - x0f1, fy1 = py1 - y0f1;
    const int sm1 = sz1 - 1;
    const int xa1 = min(max((int)x0f1, 0), sm1);
    const int xb1 = min(max((int)x0f1 + 1, 0), sm1);
    const int ya1 = min(max((int)y0f1, 0), sm1);
    const int yb1 = min(max((int)y0f1 + 1, 0), sm1);
    const int xc1 = cx ? xb1 : xa1;
    const uint4* b1 = pyr + c_off[l1] * 2;

    // ---- 4 independent loads, front-batched ----
    const uint4 ra0 = __ldg(b0 + (ya0 * sz0 + xc0) * 2 + c2);
    const uint4 rb0 = __ldg(b0 + (yb0 * sz0 + xc0) * 2 + c2);
    const uint4 ra1 = __ldg(b1 + (ya1 * sz1 + xc1) * 2 + c2);
    const uint4 rb1 = __ldg(b1 + (yb1 * sz1 + xc1) * 2 + c2);

    const unsigned msk = 0xFFFFFFFFu;
    float4 R = make_float4(0.f, 0.f, 0.f, 0.f);   // channels [c2*8 + cx*4 .. +4)

    // ---- tap 0 combine ----
    {
        const __half2 wya = __float2half2_rn(1.f - fy0);
        const __half2 wyb = __float2half2_rn(fy0);
        __half2 h0 = __hfma2(*(const __half2*)&rb0.x, wyb, __hmul2(*(const __half2*)&ra0.x, wya));
        __half2 h1 = __hfma2(*(const __half2*)&rb0.y, wyb, __hmul2(*(const __half2*)&ra0.y, wya));
        __half2 h2 = __hfma2(*(const __half2*)&rb0.z, wyb, __hmul2(*(const __half2*)&ra0.z, wya));
        __half2 h3 = __hfma2(*(const __half2*)&rb0.w, wyb, __hmul2(*(const __half2*)&ra0.w, wya));
        // send the half the partner (cx^1) needs; keep the half I need
        unsigned s0u = cx ? *(unsigned*)&h0 : *(unsigned*)&h2;
        unsigned s1u = cx ? *(unsigned*)&h1 : *(unsigned*)&h3;
        unsigned o0u = cx ? *(unsigned*)&h2 : *(unsigned*)&h0;
        unsigned o1u = cx ? *(unsigned*)&h3 : *(unsigned*)&h1;
        unsigned r0u = __shfl_xor_sync(msk, s0u, 2);
        unsigned r1u = __shfl_xor_sync(msk, s1u, 2);
        const float wm = 1.f - f;
        const float wo = (cx ? fx0 : (1.f - fx0)) * wm;   // own corner weight
        const float wp = (cx ? (1.f - fx0) : fx0) * wm;   // partner corner weight
        float2 oo0 = __half22float2(*(__half2*)&o0u);
        float2 oo1 = __half22float2(*(__half2*)&o1u);
        float2 rr0 = __half22float2(*(__half2*)&r0u);
        float2 rr1 = __half22float2(*(__half2*)&r1u);
        R.x = fmaf(wo, oo0.x, fmaf(wp, rr0.x, R.x));
        R.y = fmaf(wo, oo0.y, fmaf(wp, rr0.y, R.y));
        R.z = fmaf(wo, oo1.x, fmaf(wp, rr1.x, R.z));
        R.w = fmaf(wo, oo1.y, fmaf(wp, rr1.y, R.w));
    }
    // ---- tap 1 combine ----
    {
        const __half2 wya = __float2half2_rn(1.f - fy1);
        const __half2 wyb = __float2half2_rn(fy1);
        __half2 h0 = __hfma2(*(const __half2*)&rb1.x, wyb, __hmul2(*(const __half2*)&ra1.x, wya));
        __half2 h1 = __hfma2(*(const __half2*)&rb1.y, wyb, __hmul2(*(const __half2*)&ra1.y, wya));
        __half2 h2 = __hfma2(*(const __half2*)&rb1.z, wyb, __hmul2(*(const __half2*)&ra1.z, wya));
        __half2 h3 = __hfma2(*(const __half2*)&rb1.w, wyb, __hmul2(*(const __half2*)&ra1.w, wya));
        unsigned s0u = cx ? *(unsigned*)&h0 : *(unsigned*)&h2;
        unsigned s1u = cx ? *(unsigned*)&h1 : *(unsigned*)&h3;
        unsigned o0u = cx ? *(unsigned*)&h2 : *(unsigned*)&h0;
        unsigned o1u = cx ? *(unsigned*)&h3 : *(unsigned*)&h1;
        unsigned r0u = __shfl_xor_sync(msk, s0u, 2);
        unsigned r1u = __shfl_xor_sync(msk, s1u, 2);
        const float wo = (cx ? fx1 : (1.f - fx1)) * f;
        const float wp = (cx ? (1.f - fx1) : fx1) * f;
        float2 oo0 = __half22float2(*(__half2*)&o0u);
        float2 oo1 = __half22float2(*(__half2*)&o1u);
        float2 rr0 = __half22float2(*(__half2*)&r0u);
        float2 rr1 = __half22float2(*(__half2*)&r1u);
        R.x = fmaf(wo, oo0.x, fmaf(wp, rr0.x, R.x));
        R.y = fmaf(wo, oo0.y, fmaf(wp, rr0.y, R.y));
        R.z = fmaf(wo, oo1.x, fmaf(wp, rr1.x, R.z));
        R.w = fmaf(wo, oo1.y, fmaf(wp, rr1.y, R.w));
    }

    // evict-first streaming store: keep fm + pyramid L2-resident
    __stcs(out + ps * 4 + c2 * 2 + cx, R);
}

extern "C" void kernel_launch(void* const* d_in, const int* in_sizes, int n_in,
                              void* d_out, int out_size) {
    const float*  x     = (const float*)d_in[0];
    const float*  level = (const float*)d_in[1];
    const float4* fm    = (const float4*)d_in[2];
    float4* out = (float4*)d_out;
    const int N = in_sizes[0] / 3;
    const int N3 = N * 3;

    ds_fused<<<3 * 1024, 256>>>(fm);

    const int total = N3 * 4;
    const int threads = 256;
    sample_kernel<<<(total + threads - 1) / threads, threads>>>(x, level, out, N3);
}

// round 8
// speedup vs baseline: 1.0550x; 1.0550x over previous
#include <cuda_runtime.h>
#include <cuda_fp16.h>

// fp16 pyramid, levels 0..7. Texels/plane: 512^2 + 256^2 + ... + 4^2 = 349520.
#define T_ALL 349520
__device__ __half g_pyrh[3 * T_ALL * 16];     // 33.6 MB
__device__ float4 g_l4[3 * 1024 * 4];         // fp32 level 4 (32x32/plane), c4-sliced
__device__ unsigned g_ctr3[3];                // per-plane completion counters

// texel offset of level l (0..7) within a plane's fp16 region
__constant__ int c_off[8] = {0, 262144, 327680, 344064, 348160, 349184, 349440, 349504};

__device__ __forceinline__ void st_h4(__half* p, float4 v) {
    __half2 a = __floats2half2_rn(v.x, v.y);
    __half2 b = __floats2half2_rn(v.z, v.w);
    uint2 u;
    u.x = *reinterpret_cast<unsigned*>(&a);
    u.y = *reinterpret_cast<unsigned*>(&b);
    *reinterpret_cast<uint2*>(p) = u;
}

__device__ __forceinline__ float4 avg4(float4 a, float4 b, float4 c, float4 d) {
    float4 r;
    r.x = (a.x + b.x + c.x + d.x) * 0.25f;
    r.y = (a.y + b.y + c.y + d.y) * 0.25f;
    r.z = (a.z + b.z + c.z + d.z) * 0.25f;
    r.w = (a.w + b.w + c.w + d.w) * 0.25f;
    return r;
}

// ---------------------------------------------------------------------------
// ds_fused: block = (plane, 16x16 L0 tile). Coalesced fm load, fp16 L0 copy
// via STG.128, cascade L1..L4 in smem. Per-plane last block builds L5..L7.
// grid = 3 * 1024 blocks, 256 threads.
// ---------------------------------------------------------------------------
__global__ void __launch_bounds__(256) ds_fused(const float4* __restrict__ fm) {
    __shared__ float4 s0[1024];   // 16x16 texels x 4 f4 (16KB)
    __shared__ float4 s1[256];    // 8x8
    __shared__ float4 s2[64];     // 4x4
    __shared__ float4 s3[16];     // 2x2
    __shared__ bool   isLast;

    const int b = blockIdx.x;
    const int tile = b & 1023;
    const int plane = b >> 10;
    const int tx = tile & 31, ty = tile >> 5;
    const int tid = threadIdx.x;

    const float4* src = fm + (size_t)plane * (512 * 512 * 4);
    __half* hp = g_pyrh + (size_t)plane * T_ALL * 16;

    // L0: 512 items of (row r, texel col c, half h). Each item: 2 LDG.128 +
    // 1 STG.128 fp16 copy (coalesced 16B stores).
    #pragma unroll
    for (int i = 0; i < 2; ++i) {
        int p = i * 256 + tid;
        int h = p & 1;
        int cc = (p >> 1) & 15;
        int r = p >> 5;
        int gy = ty * 16 + r, gx = tx * 16 + cc;
        const float4* sp = src + ((size_t)gy * 512 + gx) * 4 + h * 2;
        float4 v0 = __ldg(sp);
        float4 v1 = __ldg(sp + 1);
        s0[(r * 16 + cc) * 4 + h * 2]     = v0;
        s0[(r * 16 + cc) * 4 + h * 2 + 1] = v1;
        __half2 a0 = __floats2half2_rn(v0.x, v0.y);
        __half2 a1 = __floats2half2_rn(v0.z, v0.w);
        __half2 b0 = __floats2half2_rn(v1.x, v1.y);
        __half2 b1 = __floats2half2_rn(v1.z, v1.w);
        uint4 uu;
        uu.x = *reinterpret_cast<unsigned*>(&a0);
        uu.y = *reinterpret_cast<unsigned*>(&a1);
        uu.z = *reinterpret_cast<unsigned*>(&b0);
        uu.w = *reinterpret_cast<unsigned*>(&b1);
        *reinterpret_cast<uint4*>(hp + ((size_t)gy * 512 + gx) * 16 + h * 8) = uu;
    }
    __syncthreads();

    // L1: 8x8 texels x4
    {
        int c4 = tid & 3, x = (tid >> 2) & 7, y = tid >> 5;
        float4 v = avg4(s0[((2 * y) * 16 + 2 * x) * 4 + c4],
                        s0[((2 * y) * 16 + 2 * x + 1) * 4 + c4],
                        s0[((2 * y + 1) * 16 + 2 * x) * 4 + c4],
                        s0[((2 * y + 1) * 16 + 2 * x + 1) * 4 + c4]);
        s1[tid] = v;
        st_h4(hp + (size_t)(c_off[1] + (ty * 8 + y) * 256 + tx * 8 + x) * 16 + c4 * 4, v);
    }
    __syncthreads();

    // L2: 4x4 x4
    if (tid < 64) {
        int c4 = tid & 3, x = (tid >> 2) & 3, y = tid >> 4;
        float4 v = avg4(s1[((2 * y) * 8 + 2 * x) * 4 + c4],
                        s1[((2 * y) * 8 + 2 * x + 1) * 4 + c4],
                        s1[((2 * y + 1) * 8 + 2 * x) * 4 + c4],
                        s1[((2 * y + 1) * 8 + 2 * x + 1) * 4 + c4]);
        s2[tid] = v;
        st_h4(hp + (size_t)(c_off[2] + (ty * 4 + y) * 128 + tx * 4 + x) * 16 + c4 * 4, v);
    }
    __syncthreads();

    // L3: 2x2 x4
    if (tid < 16) {
        int c4 = tid & 3, x = (tid >> 2) & 1, y = tid >> 3;
        float4 v = avg4(s2[((2 * y) * 4 + 2 * x) * 4 + c4],
                        s2[((2 * y) * 4 + 2 * x + 1) * 4 + c4],
                        s2[((2 * y + 1) * 4 + 2 * x) * 4 + c4],
                        s2[((2 * y + 1) * 4 + 2 * x + 1) * 4 + c4]);
        s3[tid] = v;
        st_h4(hp + (size_t)(c_off[3] + (ty * 2 + y) * 64 + tx * 2 + x) * 16 + c4 * 4, v);
    }
    __syncthreads();

    // L4: one texel per tile
    if (tid < 4) {
        int c4 = tid;
        float4 v = avg4(s3[0 * 4 + c4], s3[1 * 4 + c4], s3[2 * 4 + c4], s3[3 * 4 + c4]);
        st_h4(hp + (size_t)(c_off[4] + ty * 32 + tx) * 16 + c4 * 4, v);
        g_l4[((size_t)plane * 1024 + ty * 32 + tx) * 4 + c4] = v;
    }

    // ---- per-plane last block builds L5..L7 from fp32 L4 ----
    if (tid == 0) {
        __threadfence();
        unsigned c = atomicAdd(&g_ctr3[plane], 1u);
        isLast = (c == 1023u);
    }
    __syncthreads();
    if (!isLast) return;
    if (tid == 0) g_ctr3[plane] = 0;   // reset for next graph replay
    __threadfence();                   // see all blocks' g_l4 writes
    __syncthreads();

    const float4* L4 = g_l4 + (size_t)plane * 1024 * 4;
    // L5: 16x16 x4 = 1024 items, staged in s0
    for (int k = tid; k < 1024; k += 256) {
        int c4 = k & 3, x = (k >> 2) & 15, y = k >> 6;
        float4 v = avg4(L4[((2 * y) * 32 + 2 * x) * 4 + c4],
                        L4[((2 * y) * 32 + 2 * x + 1) * 4 + c4],
                        L4[((2 * y + 1) * 32 + 2 * x) * 4 + c4],
                        L4[((2 * y + 1) * 32 + 2 * x + 1) * 4 + c4]);
        s0[k] = v;
        st_h4(hp + (size_t)(c_off[5] + y * 16 + x) * 16 + c4 * 4, v);
    }
    __syncthreads();
    // L6: 8x8 x4 = 256 items
    {
        int c4 = tid & 3, x = (tid >> 2) & 7, y = tid >> 5;
        float4 v = avg4(s0[((2 * y) * 16 + 2 * x) * 4 + c4],
                        s0[((2 * y) * 16 + 2 * x + 1) * 4 + c4],
                        s0[((2 * y + 1) * 16 + 2 * x) * 4 + c4],
                        s0[((2 * y + 1) * 16 + 2 * x + 1) * 4 + c4]);
        st_h4(hp + (size_t)(c_off[6] + y * 8 + x) * 16 + c4 * 4, v);
    }
    // L7: 4x4 x4 via 4x4 box of L5
    if (tid < 64) {
        int c4 = tid & 3, x = (tid >> 2) & 3, y = tid >> 4;
        float4 acc = make_float4(0.f, 0.f, 0.f, 0.f);
        #pragma unroll
        for (int dy = 0; dy < 4; ++dy)
            #pragma unroll
            for (int dx = 0; dx < 4; ++dx) {
                float4 t = s0[((4 * y + dy) * 16 + 4 * x + dx) * 4 + c4];
                acc.x += t.x; acc.y += t.y; acc.z += t.z; acc.w += t.w;
            }
        float4 v = make_float4(acc.x * 0.0625f, acc.y * 0.0625f,
                               acc.z * 0.0625f, acc.w * 0.0625f);
        st_h4(hp + (size_t)(c_off[7] + y * 4 + x) * 16 + c4 * 4, v);
    }
}

// ---------------------------------------------------------------------------
// Sample: gridDim.y = plane (uniform per block). 4 lanes per point per plane:
// lane = (cx, c2). Each lane computes only its own corner column.
// ---------------------------------------------------------------------------
__global__ void __launch_bounds__(256) sample_kernel(
        const float* __restrict__ xin,
        const float* __restrict__ level,
        float4* __restrict__ out, int N) {
    const int t4 = blockIdx.x * blockDim.x + threadIdx.x;
    const int pt = t4 >> 2;
    if (pt >= N) return;
    const int plane = blockIdx.y;
    const int sub = t4 & 3;
    const int c2 = sub & 1;
    const int cx = sub >> 1;
    const float one_m_fcx = 1.f - (float)cx;

    const int uidx = (plane == 0) ? 1 : 0;
    const int vidx = (plane == 2) ? 1 : 2;
    const float u = __ldg(xin + pt * 3 + uidx);
    const float v = __ldg(xin + pt * 3 + vidx);

    float lvl = fminf(fmaxf(__ldg(level + pt), 0.f), 7.f);
    const float l0f = floorf(lvl);
    const float f = lvl - l0f;
    const int l0 = (int)l0f;
    const int l1 = min(l0 + 1, 7);

    const uint4* pyr = reinterpret_cast<const uint4*>(g_pyrh) + (size_t)plane * T_ALL * 2;

    // ---- tap 0 addresses (own corner only) ----
    const int sz0 = 512 >> l0;
    const float px0 = fmaf(u, (float)sz0, -0.5f);
    const float py0 = fmaf(v, (float)sz0, -0.5f);
    const float x0f0 = floorf(px0), y0f0 = floorf(py0);
    const float fx0 = px0 - x0f0, fy0 = py0 - y0f0;
    const int sm0 = sz0 - 1;
    const int xc0 = min(max((int)x0f0 + cx, 0), sm0);
    const int ya0 = min(max((int)y0f0, 0), sm0);
    const int yb0 = min(max((int)y0f0 + 1, 0), sm0);
    const uint4* b0 = pyr + c_off[l0] * 2;

    // ---- tap 1 addresses ----
    const int sz1 = 512 >> l1;
    const float px1 = fmaf(u, (float)sz1, -0.5f);
    const float py1 = fmaf(v, (float)sz1, -0.5f);
    const float x0f1 = floorf(px1), y0f1 = floorf(py1);
    const float fx1 = px1 - x0f1, fy1 = py1 - y0f1;
    const int sm1 = sz1 - 1;
    const int xc1 = min(max((int)x0f1 + cx, 0), sm1);
    const int ya1 = min(max((int)y0f1, 0), sm1);
    const int yb1 = min(max((int)y0f1 + 1, 0), sm1);
    const uint4* b1 = pyr + c_off[l1] * 2;

    // ---- 4 independent loads, front-batched ----
    const uint4 ra0 = __ldg(b0 + (ya0 * sz0 + xc0) * 2 + c2);
    const uint4 rb0 = __ldg(b0 + (yb0 * sz0 + xc0) * 2 + c2);
    const uint4 ra1 = __ldg(b1 + (ya1 * sz1 + xc1) * 2 + c2);
    const uint4 rb1 = __ldg(b1 + (yb1 * sz1 + xc1) * 2 + c2);

    const unsigned msk = 0xFFFFFFFFu;
    float4 R = make_float4(0.f, 0.f, 0.f, 0.f);   // channels [c2*8 + cx*4 .. +4)

    // ---- tap 0 combine ----
    {
        const __half2 wya = __float2half2_rn(1.f - fy0);
        const __half2 wyb = __float2half2_rn(fy0);
        __half2 h0 = __hfma2(*(const __half2*)&rb0.x, wyb, __hmul2(*(const __half2*)&ra0.x, wya));
        __half2 h1 = __hfma2(*(const __half2*)&rb0.y, wyb, __hmul2(*(const __half2*)&ra0.y, wya));
        __half2 h2 = __hfma2(*(const __half2*)&rb0.z, wyb, __hmul2(*(const __half2*)&ra0.z, wya));
        __half2 h3 = __hfma2(*(const __half2*)&rb0.w, wyb, __hmul2(*(const __half2*)&ra0.w, wya));
        unsigned s0u = cx ? *(unsigned*)&h0 : *(unsigned*)&h2;
        unsigned s1u = cx ? *(unsigned*)&h1 : *(unsigned*)&h3;
        unsigned o0u = cx ? *(unsigned*)&h2 : *(unsigned*)&h0;
        unsigned o1u = cx ? *(unsigned*)&h3 : *(unsigned*)&h1;
        unsigned r0u = __shfl_xor_sync(msk, s0u, 2);
        unsigned r1u = __shfl_xor_sync(msk, s1u, 2);
        const float wm = 1.f - f;
        const float wo = fabsf(one_m_fcx - fx0) * wm;   // own corner weight
        const float wp = wm - wo;                        // partner corner weight
        float2 oo0 = __half22float2(*(__half2*)&o0u);
        float2 oo1 = __half22float2(*(__half2*)&o1u);
        float2 rr0 = __half22float2(*(__half2*)&r0u);
        float2 rr1 = __half22float2(*(__half2*)&r1u);
        R.x = fmaf(wo, oo0.x, fmaf(wp, rr0.x, R.x));
        R.y = fmaf(wo, oo0.y, fmaf(wp, rr0.y, R.y));
        R.z = fmaf(wo, oo1.x, fmaf(wp, rr1.x, R.z));
        R.w = fmaf(wo, oo1.y, fmaf(wp, rr1.y, R.w));
    }
    // ---- tap 1 combine ----
    {
        const __half2 wya = __float2half2_rn(1.f - fy1);
        const __half2 wyb = __float2half2_rn(fy1);
        __half2 h0 = __hfma2(*(const __half2*)&rb1.x, wyb, __hmul2(*(const __half2*)&ra1.x, wya));
        __half2 h1 = __hfma2(*(const __half2*)&rb1.y, wyb, __hmul2(*(const __half2*)&ra1.y, wya));
        __half2 h2 = __hfma2(*(const __half2*)&rb1.z, wyb, __hmul2(*(const __half2*)&ra1.z, wya));
        __half2 h3 = __hfma2(*(const __half2*)&rb1.w, wyb, __hmul2(*(const __half2*)&ra1.w, wya));
        unsigned s0u = cx ? *(unsigned*)&h0 : *(unsigned*)&h2;
        unsigned s1u = cx ? *(unsigned*)&h1 : *(unsigned*)&h3;
        unsigned o0u = cx ? *(unsigned*)&h2 : *(unsigned*)&h0;
        unsigned o1u = cx ? *(unsigned*)&h3 : *(unsigned*)&h1;
        unsigned r0u = __shfl_xor_sync(msk, s0u, 2);
        unsigned r1u = __shfl_xor_sync(msk, s1u, 2);
        const float wo = fabsf(one_m_fcx - fx1) * f;
        const float wp = f - wo;
        float2 oo0 = __half22float2(*(__half2*)&o0u);
        float2 oo1 = __half22float2(*(__half2*)&o1u);
        float2 rr0 = __half22float2(*(__half2*)&r0u);
        float2 rr1 = __half22float2(*(__half2*)&r1u);
        R.x = fmaf(wo, oo0.x, fmaf(wp, rr0.x, R.x));
        R.y = fmaf(wo, oo0.y, fmaf(wp, rr0.y, R.y));
        R.z = fmaf(wo, oo1.x, fmaf(wp, rr1.x, R.z));
        R.w = fmaf(wo, oo1.y, fmaf(wp, rr1.y, R.w));
    }

    // evict-first streaming store
    const int ps = pt * 3 + plane;
    __stcs(out + ps * 4 + c2 * 2 + cx, R);
}

extern "C" void kernel_launch(void* const* d_in, const int* in_sizes, int n_in,
                              void* d_out, int out_size) {
    const float*  x     = (const float*)d_in[0];
    const float*  level = (const float*)d_in[1];
    const float4* fm    = (const float4*)d_in[2];
    float4* out = (float4*)d_out;
    const int N = in_sizes[0] / 3;

    ds_fused<<<3 * 1024, 256>>>(fm);

    dim3 grid((N * 4 + 255) / 256, 3);
    sample_kernel<<<grid, 256>>>(x, level, out, N);
}

// round 9
// speedup vs baseline: 1.0907x; 1.0339x over previous
#include <cuda_runtime.h>
#include <cuda_fp16.h>

// fp16 pyramid, levels 0..7. Texels/plane: 512^2 + 256^2 + ... + 4^2 = 349520.
#define T_ALL 349520
__device__ __half g_pyrh[3 * T_ALL * 16];     // 33.6 MB
__device__ float4 g_l4[3 * 1024 * 4];         // fp32 level 4 (32x32/plane), c4-sliced
__device__ unsigned g_ctr3[3];                // per-plane completion counters

// texel offset of level l (0..7) within a plane's fp16 region
__constant__ int c_off[8] = {0, 262144, 327680, 344064, 348160, 349184, 349440, 349504};

__device__ __forceinline__ void st_h4(__half* p, float4 v) {
    __half2 a = __floats2half2_rn(v.x, v.y);
    __half2 b = __floats2half2_rn(v.z, v.w);
    uint2 u;
    u.x = *reinterpret_cast<unsigned*>(&a);
    u.y = *reinterpret_cast<unsigned*>(&b);
    *reinterpret_cast<uint2*>(p) = u;
}

__device__ __forceinline__ float4 avg4(float4 a, float4 b, float4 c, float4 d) {
    float4 r;
    r.x = (a.x + b.x + c.x + d.x) * 0.25f;
    r.y = (a.y + b.y + c.y + d.y) * 0.25f;
    r.z = (a.z + b.z + c.z + d.z) * 0.25f;
    r.w = (a.w + b.w + c.w + d.w) * 0.25f;
    return r;
}

// ---------------------------------------------------------------------------
// ds_fused: block = (plane, 16x16 L0 tile). Coalesced fm load, fp16 L0 copy
// via STG.128, cascade L1..L4 in smem. Per-plane last block builds L5..L7.
// ---------------------------------------------------------------------------
__global__ void __launch_bounds__(256) ds_fused(const float4* __restrict__ fm) {
    __shared__ float4 s0[1024];   // 16x16 texels x 4 f4 (16KB)
    __shared__ float4 s1[256];    // 8x8
    __shared__ float4 s2[64];     // 4x4
    __shared__ float4 s3[16];     // 2x2
    __shared__ bool   isLast;

    const int b = blockIdx.x;
    const int tile = b & 1023;
    const int plane = b >> 10;
    const int tx = tile & 31, ty = tile >> 5;
    const int tid = threadIdx.x;

    const float4* src = fm + (size_t)plane * (512 * 512 * 4);
    __half* hp = g_pyrh + (size_t)plane * T_ALL * 16;

    // L0: 512 items of (row r, texel col c, half h): 2 LDG.128 + 1 STG.128.
    #pragma unroll
    for (int i = 0; i < 2; ++i) {
        int p = i * 256 + tid;
        int h = p & 1;
        int cc = (p >> 1) & 15;
        int r = p >> 5;
        int gy = ty * 16 + r, gx = tx * 16 + cc;
        const float4* sp = src + ((size_t)gy * 512 + gx) * 4 + h * 2;
        float4 v0 = __ldg(sp);
        float4 v1 = __ldg(sp + 1);
        s0[(r * 16 + cc) * 4 + h * 2]     = v0;
        s0[(r * 16 + cc) * 4 + h * 2 + 1] = v1;
        __half2 a0 = __floats2half2_rn(v0.x, v0.y);
        __half2 a1 = __floats2half2_rn(v0.z, v0.w);
        __half2 b0 = __floats2half2_rn(v1.x, v1.y);
        __half2 b1 = __floats2half2_rn(v1.z, v1.w);
        uint4 uu;
        uu.x = *reinterpret_cast<unsigned*>(&a0);
        uu.y = *reinterpret_cast<unsigned*>(&a1);
        uu.z = *reinterpret_cast<unsigned*>(&b0);
        uu.w = *reinterpret_cast<unsigned*>(&b1);
        *reinterpret_cast<uint4*>(hp + ((size_t)gy * 512 + gx) * 16 + h * 8) = uu;
    }
    __syncthreads();

    // L1: 8x8 texels x4
    {
        int c4 = tid & 3, x = (tid >> 2) & 7, y = tid >> 5;
        float4 v = avg4(s0[((2 * y) * 16 + 2 * x) * 4 + c4],
                        s0[((2 * y) * 16 + 2 * x + 1) * 4 + c4],
                        s0[((2 * y + 1) * 16 + 2 * x) * 4 + c4],
                        s0[((2 * y + 1) * 16 + 2 * x + 1) * 4 + c4]);
        s1[tid] = v;
        st_h4(hp + (size_t)(c_off[1] + (ty * 8 + y) * 256 + tx * 8 + x) * 16 + c4 * 4, v);
    }
    __syncthreads();

    // L2: 4x4 x4
    if (tid < 64) {
        int c4 = tid & 3, x = (tid >> 2) & 3, y = tid >> 4;
        float4 v = avg4(s1[((2 * y) * 8 + 2 * x) * 4 + c4],
                        s1[((2 * y) * 8 + 2 * x + 1) * 4 + c4],
                        s1[((2 * y + 1) * 8 + 2 * x) * 4 + c4],
                        s1[((2 * y + 1) * 8 + 2 * x + 1) * 4 + c4]);
        s2[tid] = v;
        st_h4(hp + (size_t)(c_off[2] + (ty * 4 + y) * 128 + tx * 4 + x) * 16 + c4 * 4, v);
    }
    __syncthreads();

    // L3: 2x2 x4
    if (tid < 16) {
        int c4 = tid & 3, x = (tid >> 2) & 1, y = tid >> 3;
        float4 v = avg4(s2[((2 * y) * 4 + 2 * x) * 4 + c4],
                        s2[((2 * y) * 4 + 2 * x + 1) * 4 + c4],
                        s2[((2 * y + 1) * 4 + 2 * x) * 4 + c4],
                        s2[((2 * y + 1) * 4 + 2 * x + 1) * 4 + c4]);
        s3[tid] = v;
        st_h4(hp + (size_t)(c_off[3] + (ty * 2 + y) * 64 + tx * 2 + x) * 16 + c4 * 4, v);
    }
    __syncthreads();

    // L4: one texel per tile
    if (tid < 4) {
        int c4 = tid;
        float4 v = avg4(s3[0 * 4 + c4], s3[1 * 4 + c4], s3[2 * 4 + c4], s3[3 * 4 + c4]);
        st_h4(hp + (size_t)(c_off[4] + ty * 32 + tx) * 16 + c4 * 4, v);
        g_l4[((size_t)plane * 1024 + ty * 32 + tx) * 4 + c4] = v;
    }

    // ---- per-plane last block builds L5..L7 from fp32 L4 ----
    if (tid == 0) {
        __threadfence();
        unsigned c = atomicAdd(&g_ctr3[plane], 1u);
        isLast = (c == 1023u);
    }
    __syncthreads();
    if (!isLast) return;
    if (tid == 0) g_ctr3[plane] = 0;   // reset for next graph replay
    __threadfence();                   // see all blocks' g_l4 writes
    __syncthreads();

    const float4* L4 = g_l4 + (size_t)plane * 1024 * 4;
    // L5: 16x16 x4 = 1024 items, staged in s0
    for (int k = tid; k < 1024; k += 256) {
        int c4 = k & 3, x = (k >> 2) & 15, y = k >> 6;
        float4 v = avg4(L4[((2 * y) * 32 + 2 * x) * 4 + c4],
                        L4[((2 * y) * 32 + 2 * x + 1) * 4 + c4],
                        L4[((2 * y + 1) * 32 + 2 * x) * 4 + c4],
                        L4[((2 * y + 1) * 32 + 2 * x + 1) * 4 + c4]);
        s0[k] = v;
        st_h4(hp + (size_t)(c_off[5] + y * 16 + x) * 16 + c4 * 4, v);
    }
    __syncthreads();
    // L6: 8x8 x4 = 256 items
    {
        int c4 = tid & 3, x = (tid >> 2) & 7, y = tid >> 5;
        float4 v = avg4(s0[((2 * y) * 16 + 2 * x) * 4 + c4],
                        s0[((2 * y) * 16 + 2 * x + 1) * 4 + c4],
                        s0[((2 * y + 1) * 16 + 2 * x) * 4 + c4],
                        s0[((2 * y + 1) * 16 + 2 * x + 1) * 4 + c4]);
        st_h4(hp + (size_t)(c_off[6] + y * 8 + x) * 16 + c4 * 4, v);
    }
    // L7: 4x4 x4 via 4x4 box of L5
    if (tid < 64) {
        int c4 = tid & 3, x = (tid >> 2) & 3, y = tid >> 4;
        float4 acc = make_float4(0.f, 0.f, 0.f, 0.f);
        #pragma unroll
        for (int dy = 0; dy < 4; ++dy)
            #pragma unroll
            for (int dx = 0; dx < 4; ++dx) {
                float4 t = s0[((4 * y + dy) * 16 + 4 * x + dx) * 4 + c4];
                acc.x += t.x; acc.y += t.y; acc.z += t.z; acc.w += t.w;
            }
        float4 v = make_float4(acc.x * 0.0625f, acc.y * 0.0625f,
                               acc.z * 0.0625f, acc.w * 0.0625f);
        st_h4(hp + (size_t)(c_off[7] + y * 4 + x) * 16 + c4 * 4, v);
    }
}

// ---------------------------------------------------------------------------
// Sample: gridDim.y = plane. 4 lanes per (point, plane): lane = (cx, c2).
// Quad-cooperative input load + pre-weighted half2 exchange.
// ---------------------------------------------------------------------------
__global__ void __launch_bounds__(256) sample_kernel(
        const float* __restrict__ xin,
        const float* __restrict__ level,
        float4* __restrict__ out, int N) {
    const int t4 = blockIdx.x * blockDim.x + threadIdx.x;
    const int pt = t4 >> 2;
    if (pt >= N) return;
    const int plane = blockIdx.y;
    const int sub = t4 & 3;
    const int c2 = sub & 1;
    const int cx = sub >> 1;
    const float one_m_fcx = 1.f - (float)cx;
    const unsigned msk = 0xFFFFFFFFu;

    // quad-cooperative load: subs 0..2 -> xin[pt*3+sub], sub 3 -> level[pt]
    const float* addr = (sub < 3) ? (xin + pt * 3 + sub) : (level + pt);
    const float val = __ldg(addr);
    const int uidx = (plane == 0) ? 1 : 0;
    const int vidx = (plane == 2) ? 1 : 2;
    const float u   = __shfl_sync(msk, val, uidx, 4);
    const float v   = __shfl_sync(msk, val, vidx, 4);
    float lvl       = __shfl_sync(msk, val, 3, 4);

    lvl = fminf(fmaxf(lvl, 0.f), 7.f);
    const float l0f = floorf(lvl);
    const float f = lvl - l0f;
    const int l0 = (int)l0f;
    const int l1 = min(l0 + 1, 7);

    const uint4* pyr = reinterpret_cast<const uint4*>(g_pyrh) + (size_t)plane * T_ALL * 2;

    // ---- tap 0 addresses (u,v in [0,1] => x0 in [-1, sz-1]: single clamps) ----
    const int sz0 = 512 >> l0;
    const float px0 = fmaf(u, (float)sz0, -0.5f);
    const float py0 = fmaf(v, (float)sz0, -0.5f);
    const float x0f0 = floorf(px0), y0f0 = floorf(py0);
    const float fx0 = px0 - x0f0, fy0 = py0 - y0f0;
    const int xc0 = min(max((int)x0f0 + cx, 0), sz0 - 1);
    const int ya0 = max((int)y0f0, 0);
    const int yb0 = min((int)y0f0 + 1, sz0 - 1);
    const uint4* b0 = pyr + c_off[l0] * 2;

    // ---- tap 1 addresses ----
    const int sz1 = 512 >> l1;
    const float px1 = fmaf(u, (float)sz1, -0.5f);
    const float py1 = fmaf(v, (float)sz1, -0.5f);
    const float x0f1 = floorf(px1), y0f1 = floorf(py1);
    const float fx1 = px1 - x0f1, fy1 = py1 - y0f1;
    const int xc1 = min(max((int)x0f1 + cx, 0), sz1 - 1);
    const int ya1 = max((int)y0f1, 0);
    const int yb1 = min((int)y0f1 + 1, sz1 - 1);
    const uint4* b1 = pyr + c_off[l1] * 2;

    // ---- 4 independent loads, front-batched ----
    const uint4 ra0 = __ldg(b0 + (ya0 * sz0 + xc0) * 2 + c2);
    const uint4 rb0 = __ldg(b0 + (yb0 * sz0 + xc0) * 2 + c2);
    const uint4 ra1 = __ldg(b1 + (ya1 * sz1 + xc1) * 2 + c2);
    const uint4 rb1 = __ldg(b1 + (yb1 * sz1 + xc1) * 2 + c2);

    float4 R;

    // ---- tap 0: row blend, pre-weight in half2, exchange, add ----
    {
        const __half2 wya = __float2half2_rn(1.f - fy0);
        const __half2 wyb = __float2half2_rn(fy0);
        __half2 h0 = __hfma2(*(const __half2*)&rb0.x, wyb, __hmul2(*(const __half2*)&ra0.x, wya));
        __half2 h1 = __hfma2(*(const __half2*)&rb0.y, wyb, __hmul2(*(const __half2*)&ra0.y, wya));
        __half2 h2 = __hfma2(*(const __half2*)&rb0.z, wyb, __hmul2(*(const __half2*)&ra0.z, wya));
        __half2 h3 = __hfma2(*(const __half2*)&rb0.w, wyb, __hmul2(*(const __half2*)&ra0.w, wya));
        const float wo = fabsf(one_m_fcx - fx0) * (1.f - f);   // own-corner * mip weight
        const __half2 woh = __float2half2_rn(wo);
        h0 = __hmul2(h0, woh);
        h1 = __hmul2(h1, woh);
        h2 = __hmul2(h2, woh);
        h3 = __hmul2(h3, woh);
        // lane cx owns channel sub-slice cx*4..+4: keep (g0,g1) if cx==0 else (g2,g3)
        unsigned send0 = cx ? *(unsigned*)&h0 : *(unsigned*)&h2;
        unsigned send1 = cx ? *(unsigned*)&h1 : *(unsigned*)&h3;
        unsigned keep0 = cx ? *(unsigned*)&h2 : *(unsigned*)&h0;
        unsigned keep1 = cx ? *(unsigned*)&h3 : *(unsigned*)&h1;
        unsigned recv0 = __shfl_xor_sync(msk, send0, 2);
        unsigned recv1 = __shfl_xor_sync(msk, send1, 2);
        __half2 s0h = __hadd2(*(__half2*)&keep0, *(__half2*)&recv0);
        __half2 s1h = __hadd2(*(__half2*)&keep1, *(__half2*)&recv1);
        float2 f01 = __half22float2(s0h);
        float2 f23 = __half22float2(s1h);
        R = make_float4(f01.x, f01.y, f23.x, f23.y);
    }
    // ---- tap 1 ----
    {
        const __half2 wya = __float2half2_rn(1.f - fy1);
        const __half2 wyb = __float2half2_rn(fy1);
        __half2 h0 = __hfma2(*(const __half2*)&rb1.x, wyb, __hmul2(*(const __half2*)&ra1.x, wya));
        __half2 h1 = __hfma2(*(const __half2*)&rb1.y, wyb, __hmul2(*(const __half2*)&ra1.y, wya));
        __half2 h2 = __hfma2(*(const __half2*)&rb1.z, wyb, __hmul2(*(const __half2*)&ra1.z, wya));
        __half2 h3 = __hfma2(*(const __half2*)&rb1.w, wyb, __hmul2(*(const __half2*)&ra1.w, wya));
        const float wo = fabsf(one_m_fcx - fx1) * f;
        const __half2 woh = __float2half2_rn(wo);
        h0 = __hmul2(h0, woh);
        h1 = __hmul2(h1, woh);
        h2 = __hmul2(h2, woh);
        h3 = __hmul2(h3, woh);
        unsigned send0 = cx ? *(unsigned*)&h0 : *(unsigned*)&h2;
        unsigned send1 = cx ? *(unsigned*)&h1 : *(unsigned*)&h3;
        unsigned keep0 = cx ? *(unsigned*)&h2 : *(unsigned*)&h0;
        unsigned keep1 = cx ? *(unsigned*)&h3 : *(unsigned*)&h1;
        unsigned recv0 = __shfl_xor_sync(msk, send0, 2);
        unsigned recv1 = __shfl_xor_sync(msk, send1, 2);
        __half2 s0h = __hadd2(*(__half2*)&keep0, *(__half2*)&recv0);
        __half2 s1h = __hadd2(*(__half2*)&keep1, *(__half2*)&recv1);
        float2 f01 = __half22float2(s0h);
        float2 f23 = __half22float2(s1h);
        R.x += f01.x; R.y += f01.y; R.z += f23.x; R.w += f23.y;
    }

    // evict-first streaming store (channels [c2*8 + cx*4 .. +4))
    const int ps = pt * 3 + plane;
    __stcs(out + ps * 4 + c2 * 2 + cx, R);
}

extern "C" void kernel_launch(void* const* d_in, const int* in_sizes, int n_in,
                              void* d_out, int out_size) {
    const float*  x     = (const float*)d_in[0];
    const float*  level = (const float*)d_in[1];
    const float4* fm    = (const float4*)d_in[2];
    float4* out = (float4*)d_out;
    const int N = in_sizes[0] / 3;

    ds_fused<<<3 * 1024, 256>>>(fm);

    dim3 grid((N * 4 + 255) / 256, 3);
    sample_kernel<<<grid, 256>>>(x, level, out, N);
}